// round 10
// baseline (speedup 1.0000x reference)
#include <cuda_runtime.h>
#include <cuda_bf16.h>

// DE_NN_35820027249305: per-l tiny MLP chain (1 -> 4 -> 8 -> 4 -> 1, ReLU)
// over X of shape (44, 1, 400000).
//
// Collapse (input channel dim = 1, ReLU positively homogeneous):
//   out = x * (x >= 0 ? S_plus[l] : -S_minus[l])
// with the 88 scalars depending only on the weights.
//
// R9: single fused kernel, but the collapsed-network evaluation is
// DISTRIBUTED across warp-0 lanes (lanes 0-15 sign +, 16-31 sign -; 8 lanes
// per group compute one q_j each, 4 lanes reduce one r_k via shuffles, lane 0
// reduces S). Peak live registers on the weight path drop from ~25 to ~10,
// restoring occupancy (~75%) that R7/R8's monolithic chain destroyed.
// X loads are issued first so the weight chain + barrier hide under them.

#define NP_L   44
#define B_ELEM 400000
#define B_VEC4 (B_ELEM / 4)        // 100000 float4 per l
#define VPT    4                   // float4 per thread
#define TPB    256
#define F4_PER_BLOCK (TPB * VPT)   // 1024

__global__ void __launch_bounds__(TPB)
DE_NN_fused_kernel(const float* __restrict__ X,
                   const float* __restrict__ lin1,   // (44, 4, 1)
                   const float* __restrict__ lin2,   // (44, 8, 4)
                   const float* __restrict__ lin3,   // (44, 4, 8)
                   const float* __restrict__ lin4,   // (44, 1, 4)
                   float* __restrict__ out)
{
    __shared__ float sc[2];     // sc[0] = S(+1), sc[1] = -S(-1)

    const int l    = blockIdx.y;
    const int base = blockIdx.x * F4_PER_BLOCK + threadIdx.x;

    const float4* __restrict__ xp =
        reinterpret_cast<const float4*>(X + (size_t)l * B_ELEM);
    float4* __restrict__ op =
        reinterpret_cast<float4*>(out + (size_t)l * B_ELEM);

    // ---- 1. Issue all X loads first (front-batched, MLP_p1 = 4) ----------
    float4 v[VPT];
    #pragma unroll
    for (int i = 0; i < VPT; i++) {
        const int idx = base + i * TPB;
        if (idx < B_VEC4) v[i] = xp[idx];
    }

    // ---- 2. Warp 0: distributed collapsed network, register-light --------
    if (threadIdx.x < 32) {
        const int   lane = threadIdx.x;
        const int   grp  = lane >> 4;           // 0: sign +, 1: sign -
        const int   lid  = lane & 15;
        const int   gb   = grp << 4;            // group base lane
        const float sign = grp ? -1.0f : 1.0f;

        // Layer 1 (broadcast load, 4 regs)
        const float4 w1 = *reinterpret_cast<const float4*>(lin1 + l * 4);
        const float p0 = fmaxf(sign * w1.x, 0.0f);
        const float p1 = fmaxf(sign * w1.y, 0.0f);
        const float p2 = fmaxf(sign * w1.z, 0.0f);
        const float p3 = fmaxf(sign * w1.w, 0.0f);

        // Layer 2: lane (gb + j), j = lid&7, computes q_j (1 live reg)
        const int j8 = lid & 7;
        const float4 w2 =
            reinterpret_cast<const float4*>(lin2 + l * 32)[j8];
        float q = w2.x * p0;
        q = fmaf(w2.y, p1, q);
        q = fmaf(w2.z, p2, q);
        q = fmaf(w2.w, p3, q);
        q = fmaxf(q, 0.0f);

        // Layer 3: lane (gb + k), k = lid&3, reduces r_k via shuffles
        const int k4 = lid & 3;
        const float* w3row = lin3 + l * 32 + k4 * 8;
        float r = 0.0f;
        #pragma unroll
        for (int j = 0; j < 8; j++) {
            const float qj = __shfl_sync(0xffffffffu, q, gb + j);
            r = fmaf(w3row[j], qj, r);
        }
        r = fmaxf(r, 0.0f);

        // Layer 4: every lane reduces S (only gb lane's value is used)
        const float* w4 = lin4 + l * 4;
        float S = 0.0f;
        #pragma unroll
        for (int k = 0; k < 4; k++) {
            const float rk = __shfl_sync(0xffffffffu, r, gb + k);
            S = fmaf(w4[k], rk, S);
        }

        if (lid == 0) sc[grp] = grp ? -S : S;
    }
    __syncthreads();

    const float c0 = sc[0];   // multiplier for x >= 0
    const float c1 = sc[1];   // multiplier for x <  0

    // ---- 3. Branch-free epilogue + stores --------------------------------
    #pragma unroll
    for (int i = 0; i < VPT; i++) {
        const int idx = base + i * TPB;
        if (idx < B_VEC4) {
            const float4 x = v[i];
            float4 o;
            // x*(x>=0?c0:c1) == max(x,0)*c0 + min(x,0)*c1
            o.x = fmaf(fmaxf(x.x, 0.0f), c0, fminf(x.x, 0.0f) * c1);
            o.y = fmaf(fmaxf(x.y, 0.0f), c0, fminf(x.y, 0.0f) * c1);
            o.z = fmaf(fmaxf(x.z, 0.0f), c0, fminf(x.z, 0.0f) * c1);
            o.w = fmaf(fmaxf(x.w, 0.0f), c0, fminf(x.w, 0.0f) * c1);
            op[idx] = o;
        }
    }
}

extern "C" void kernel_launch(void* const* d_in, const int* in_sizes, int n_in,
                              void* d_out, int out_size)
{
    const float* X  = (const float*)d_in[0];
    const float* l1 = (const float*)d_in[1];
    const float* l2 = (const float*)d_in[2];
    const float* l3 = (const float*)d_in[3];
    const float* l4 = (const float*)d_in[4];
    float* out      = (float*)d_out;

    dim3 grid((B_VEC4 + F4_PER_BLOCK - 1) / F4_PER_BLOCK, NP_L);  // (98, 44)
    DE_NN_fused_kernel<<<grid, TPB>>>(X, l1, l2, l3, l4, out);
}

// round 15
// speedup vs baseline: 1.1688x; 1.1688x over previous
#include <cuda_runtime.h>
#include <cuda_bf16.h>

// DE_NN_35820027249305: per-l tiny MLP chain (1 -> 4 -> 8 -> 4 -> 1, ReLU)
// over X of shape (44, 1, 400000).
//
// Collapse (input channel dim = 1, ReLU positively homogeneous):
//   out = x * (x >= 0 ? S_plus[l] : -S_minus[l])
// with the 88 scalars depending only on the weights.
//
// R10: single fused kernel, NO BARRIER. Every warp redundantly computes both
// collapsed scales with a distributed lane scheme (lanes 0-15 sign +, lanes
// 16-31 sign -; one q_j per lane, shfl reductions for r_k and S), then grabs
// c0/c1 with two shuffles. Each warp's weight chain hides under its own
// front-batched X loads — no block-wide serialization, stream-kernel-class
// register pressure (~36) and occupancy (~80%).

#define NP_L   44
#define B_ELEM 400000
#define B_VEC4 (B_ELEM / 4)        // 100000 float4 per l
#define VPT    4                   // float4 per thread
#define TPB    256
#define F4_PER_BLOCK (TPB * VPT)   // 1024

__global__ void __launch_bounds__(TPB)
DE_NN_fused_kernel(const float* __restrict__ X,
                   const float* __restrict__ lin1,   // (44, 4, 1)
                   const float* __restrict__ lin2,   // (44, 8, 4)
                   const float* __restrict__ lin3,   // (44, 4, 8)
                   const float* __restrict__ lin4,   // (44, 1, 4)
                   float* __restrict__ out)
{
    const int l    = blockIdx.y;
    const int base = blockIdx.x * F4_PER_BLOCK + threadIdx.x;

    const float4* __restrict__ xp =
        reinterpret_cast<const float4*>(X + (size_t)l * B_ELEM);
    float4* __restrict__ op =
        reinterpret_cast<float4*>(out + (size_t)l * B_ELEM);

    // ---- 1. Issue all X loads first (front-batched, MLP_p1 = 4) ----------
    float4 v[VPT];
    #pragma unroll
    for (int i = 0; i < VPT; i++) {
        const int idx = base + i * TPB;
        if (idx < B_VEC4) v[i] = xp[idx];
    }

    // ---- 2. Per-warp distributed collapsed network (no smem, no barrier) -
    // All 32 lanes active; lanes 0-15 evaluate sign +, 16-31 sign -.
    const int   lane = threadIdx.x & 31;
    const int   grp  = lane >> 4;            // 0: +, 1: -
    const int   gb   = grp << 4;             // group base lane
    const float sign = grp ? -1.0f : 1.0f;

    // Layer 1 (warp-broadcast load)
    const float4 w1 = *reinterpret_cast<const float4*>(lin1 + l * 4);
    const float p0 = fmaxf(sign * w1.x, 0.0f);
    const float p1 = fmaxf(sign * w1.y, 0.0f);
    const float p2 = fmaxf(sign * w1.z, 0.0f);
    const float p3 = fmaxf(sign * w1.w, 0.0f);

    // Layer 2: lane gb+j (j = lane&7) computes q_j
    {
        const float4 w2 =
            reinterpret_cast<const float4*>(lin2 + l * 32)[lane & 7];
        float q = w2.x * p0;
        q = fmaf(w2.y, p1, q);
        q = fmaf(w2.z, p2, q);
        q = fmaf(w2.w, p3, q);
        q = fmaxf(q, 0.0f);

        // Layer 3: lane gb+k (k = lane&3) reduces r_k via shuffles
        const float* w3row = lin3 + l * 32 + (lane & 3) * 8;
        float r = 0.0f;
        #pragma unroll
        for (int j = 0; j < 8; j++) {
            const float qj = __shfl_sync(0xffffffffu, q, gb + j);
            r = fmaf(w3row[j], qj, r);
        }
        r = fmaxf(r, 0.0f);

        // Layer 4: every lane reduces its group's S
        const float* w4 = lin4 + l * 4;
        float S = 0.0f;
        #pragma unroll
        for (int k = 0; k < 4; k++) {
            const float rk = __shfl_sync(0xffffffffu, r, gb + k);
            S = fmaf(w4[k], rk, S);
        }

        // Broadcast both group results to all lanes.
        q = S;                                        // reuse reg
        const float c0 = __shfl_sync(0xffffffffu, q, 0);    // S(+1)
        const float c1 = -__shfl_sync(0xffffffffu, q, 16);  // -S(-1)

        // ---- 3. Branch-free epilogue + stores ----------------------------
        #pragma unroll
        for (int i = 0; i < VPT; i++) {
            const int idx = base + i * TPB;
            if (idx < B_VEC4) {
                const float4 x = v[i];
                float4 o;
                // x*(x>=0?c0:c1) == max(x,0)*c0 + min(x,0)*c1
                o.x = fmaf(fmaxf(x.x, 0.0f), c0, fminf(x.x, 0.0f) * c1);
                o.y = fmaf(fmaxf(x.y, 0.0f), c0, fminf(x.y, 0.0f) * c1);
                o.z = fmaf(fmaxf(x.z, 0.0f), c0, fminf(x.z, 0.0f) * c1);
                o.w = fmaf(fmaxf(x.w, 0.0f), c0, fminf(x.w, 0.0f) * c1);
                op[idx] = o;
            }
        }
    }
}

extern "C" void kernel_launch(void* const* d_in, const int* in_sizes, int n_in,
                              void* d_out, int out_size)
{
    const float* X  = (const float*)d_in[0];
    const float* l1 = (const float*)d_in[1];
    const float* l2 = (const float*)d_in[2];
    const float* l3 = (const float*)d_in[3];
    const float* l4 = (const float*)d_in[4];
    float* out      = (float*)d_out;

    dim3 grid((B_VEC4 + F4_PER_BLOCK - 1) / F4_PER_BLOCK, NP_L);  // (98, 44)
    DE_NN_fused_kernel<<<grid, TPB>>>(X, l1, l2, l3, l4, out);
}